// round 4
// baseline (speedup 1.0000x reference)
#include <cuda_runtime.h>

#define CHUNK_M 8
#define TP_F    (CHUNK_M * 238)            // 1904 floats = 7616 B
#define FAN_F   (CHUNK_M * 80)             // 640  floats = 2560 B
#define RED_F   (CHUNK_M * 34)             // 272  floats = 1088 B
#define STAGE_F (TP_F + FAN_F + RED_F)     // 2816 floats = 11264 B
#define STAGES  3

__device__ __forceinline__ void cp16(float* s, const float* g) {
    unsigned sa = (unsigned)__cvta_generic_to_shared(s);
    asm volatile("cp.async.cg.shared.global [%0], [%1], 16;\n" :: "r"(sa), "l"(g));
}

template<int N>
__device__ __forceinline__ void wait_grp() {
    asm volatile("cp.async.wait_group %0;\n" :: "n"(N));
}

// 2^x for x in ~[-4, 1], FMA-pipe only. Degree-6 poly, rel err ~1e-7.
__device__ __forceinline__ float exp2_fast(float x) {
    float r = rintf(x);
    float f = x - r;
    float p = 1.5403530e-4f;
    p = fmaf(p, f, 1.3333558e-3f);
    p = fmaf(p, f, 9.6181291e-3f);
    p = fmaf(p, f, 5.5504109e-2f);
    p = fmaf(p, f, 2.4022651e-1f);
    p = fmaf(p, f, 6.9314718e-1f);
    p = fmaf(p, f, 1.0f);
    return __int_as_float(__float_as_int(p) + ((int)r << 23));
}

// 1/d for positive normal d, FMA-pipe only (bit-trick seed + 3 Newton steps).
__device__ __forceinline__ float rcp_fast(float d) {
    float x = __int_as_float(0x7EF311C3 - __float_as_int(d));
    x = x * fmaf(-d, x, 2.0f);
    x = x * fmaf(-d, x, 2.0f);
    x = x * fmaf(-d, x, 2.0f);
    return x;
}

// One block per (n, action a): 64 m's in 8 chunks of 8, 3-stage cp.async ring.
// 256 threads = 8 warps; warp w handles m-local w of each chunk.
// Lane l handles tile l (and tile l+32 for l<2); full-warp butterfly.
// 6 CTAs/SM (smem ~35.5 KB, regs capped by launch_bounds).
__global__ __launch_bounds__(256, 6)
void k_main(const float* __restrict__ meta,
            const float* __restrict__ wall,
            const float* __restrict__ tp,
            const float* __restrict__ fp,
            const float* __restrict__ rp,
            const float* __restrict__ W,
            const float* __restrict__ b,
            const float* __restrict__ fanc,
            const float* __restrict__ fanm,
            const float* __restrict__ tilec,
            float* __restrict__ outm,
            float* __restrict__ outw) {
    __shared__ __align__(16) float s_buf[STAGES][STAGE_F];
    __shared__ float s_fc[80];
    __shared__ float s_l[34];
    __shared__ float s_s[34 * 8];
    __shared__ float s_f[8];
    __shared__ float s_mx[34];

    const int tid  = threadIdx.x;
    const int bid  = blockIdx.x;
    const int nIdx = bid / 5;
    const int a    = bid - nIdx * 5;
    const int w    = tid >> 5;
    const int l    = tid & 31;

    const size_t mstart = (size_t)nIdx * 320 + a * 64;

    // ---- issue chunks 0..2 into stages 0..2 (loads fly during prologue math) ----
    #pragma unroll
    for (int c = 0; c < STAGES; c++) {
        const size_t m0 = mstart + (size_t)c * CHUNK_M;
        const float* g0 = tp + m0 * 238;
        const float* g1 = fp + m0 * 80;
        const float* g2 = rp + m0 * 34;
        float* dst = &s_buf[c][0];
        for (int i = tid; i < 476; i += 256) cp16(dst + i * 4,                 g0 + i * 4);
        for (int i = tid; i < 160; i += 256) cp16(dst + TP_F + i * 4,          g1 + i * 4);
        for (int i = tid; i < 68;  i += 256) cp16(dst + TP_F + FAN_F + i * 4,  g2 + i * 4);
        asm volatile("cp.async.commit_group;\n" ::);
    }

    // fused prob_throw: per-tile Linear(11,1) then log2 (hidden under loads)
    if (tid < 34) {
        float p = b[0];
        const float* mt = meta + nIdx * 6;
        #pragma unroll
        for (int c = 0; c < 6; c++) p = fmaf(mt[c], W[c], p);
        const float* wl = wall + ((size_t)nIdx * 34 + tid) * 5;
        #pragma unroll
        for (int j = 0; j < 5; j++) p = fmaf(wl[j], W[6 + j], p);
        s_l[tid] = log2f(p);
    }
    if (tid >= 64 && tid < 144) {
        int j = tid - 64;
        s_fc[j] = fanc[j] * fanm[j];
    }
    __syncthreads();

    const float lA  = s_l[l];
    const float lB  = (l < 2) ? s_l[l + 32] : 0.f;
    const float fcA = s_fc[l];
    const float fcB = s_fc[l + 32];
    const float fcC = (l < 16) ? s_fc[l + 64] : 0.f;

    float accA = 0.f, accB = 0.f, facc = 0.f;

    #pragma unroll
    for (int k = 0; k < 8; k++) {
        // exact pending counts: chunks committed so far = 3 + min(k,5)
        if (k <= 5)      wait_grp<2>();
        else if (k == 6) wait_grp<1>();
        else             wait_grp<0>();
        __syncthreads();

        const int s = k % STAGES;
        const float* base = &s_buf[s][0];
        const float* tpb = base + w * 238;
        const float* fnb = base + TP_F + w * 80;
        const float* rdb = base + TP_F + FAN_F + w * 34;

        // fan preference partial sum (80 over 32 lanes)
        float fs = fmaf(fnb[l], fcA, fnb[l + 32] * fcB);
        if (l < 16) fs = fmaf(fnb[l + 64], fcC, fs);

        // terms_summed = t0*p^tnc + t6 + (t3*t2/t4)*t5
        //            == ((t0*e + t6)*t4 + t3*t2*t5) / t4   (single hoisted divide)
        float pn, phd;
        {
            const float* c = tpb + l * 7;
            float e = exp2_fast(c[1] * lA);
            pn  = fmaf(fmaf(c[0], e, c[6]), c[4], c[3] * c[2] * c[5]);
            phd = c[4];
        }
        if (l < 2) {
            const float* c = tpb + (l + 32) * 7;
            float e = exp2_fast(c[1] * lB);
            pn  *= fmaf(fmaf(c[0], e, c[6]), c[4], c[3] * c[2] * c[5]);
            phd *= c[4];
        }

        // full-warp butterfly: product(pn), product(phd), sum(fs)
        #pragma unroll
        for (int o = 16; o >= 1; o >>= 1) {
            pn  *= __shfl_xor_sync(0xffffffffu, pn,  o);
            phd *= __shfl_xor_sync(0xffffffffu, phd, o);
            fs  += __shfl_xor_sync(0xffffffffu, fs,  o);
        }

        const float fpt = pn * rcp_fast(phd) * 100.f * fs;

        accA = fmaf(rdb[l], fpt, accA);
        if (l < 2) accB = fmaf(rdb[l + 32], fpt, accB);
        facc += fpt;

        __syncthreads();   // all warps done reading stage s

        if (k < 5) {       // refill stage s with chunk k+3
            const size_t m0 = mstart + (size_t)(k + 3) * CHUNK_M;
            const float* g0 = tp + m0 * 238;
            const float* g1 = fp + m0 * 80;
            const float* g2 = rp + m0 * 34;
            float* dst = &s_buf[s][0];
            for (int i = tid; i < 476; i += 256) cp16(dst + i * 4,                g0 + i * 4);
            for (int i = tid; i < 160; i += 256) cp16(dst + TP_F + i * 4,         g1 + i * 4);
            for (int i = tid; i < 68;  i += 256) cp16(dst + TP_F + FAN_F + i * 4, g2 + i * 4);
            asm volatile("cp.async.commit_group;\n" ::);
        }
    }

    // ---- cross-warp reduction ----
    s_s[l * 8 + w] = accA;
    if (l < 2) s_s[(l + 32) * 8 + w] = accB;
    if (l == 0) s_f[w] = facc;
    __syncthreads();

    if (tid < 34) {
        float tb = 0.f;
        #pragma unroll
        for (int g = 0; g < 8; g++) tb += s_s[tid * 8 + g];
        if (a == 0) outw[nIdx * 34 + tid] = tb * tilec[tid];
        s_mx[tid] = tb;
    }
    __syncthreads();

    if (tid == 0) {
        float v;
        if (a == 0) {
            float fps = 0.f;
            #pragma unroll
            for (int g = 0; g < 8; g++) fps += s_f[g];
            v = fps;   // final_prob_ops[:,0] overrides slot 0
        } else {
            float mx = s_mx[0];
            #pragma unroll
            for (int t = 1; t < 34; t++) mx = fmaxf(mx, s_mx[t]);
            v = mx;
        }
        outm[nIdx * 5 + a] = v;
    }
}

extern "C" void kernel_launch(void* const* d_in, const int* in_sizes, int n_in,
                              void* d_out, int out_size) {
    const float* meta  = (const float*)d_in[0];
    const float* wall  = (const float*)d_in[1];
    const float* tp    = (const float*)d_in[2];
    const float* fp    = (const float*)d_in[3];
    const float* rp    = (const float*)d_in[4];
    // d_in[5] (count_prep), d_in[6] (chi_peng_count_remain) unused by the reference
    const float* W     = (const float*)d_in[7];
    const float* b     = (const float*)d_in[8];
    const float* fanc  = (const float*)d_in[9];
    const float* fanm  = (const float*)d_in[10];
    const float* tilec = (const float*)d_in[11];

    int n = in_sizes[0] / 6;   // 1024

    float* outm = (float*)d_out;          // (n,5)
    float* outw = outm + (size_t)n * 5;   // (n,34)

    k_main<<<n * 5, 256>>>(meta, wall, tp, fp, rp, W, b, fanc, fanm, tilec, outm, outw);
}

// round 5
// speedup vs baseline: 1.0118x; 1.0118x over previous
#include <cuda_runtime.h>

// Per stage: 16 m * (34*7) tp | 16 m * 80 fan | 16 m * 34 red
#define TP_OFF   0
#define FAN_OFF  3808
#define RED_OFF  5088
#define STAGE_F  5632

__device__ __forceinline__ void cp16(float* s, const float* g) {
    unsigned sa = (unsigned)__cvta_generic_to_shared(s);
    asm volatile("cp.async.cg.shared.global [%0], [%1], 16;\n" :: "r"(sa), "l"(g));
}

// 2^x for x in ~[-4, 1], FMA-pipe only. Degree-6 poly, rel err ~1e-7.
__device__ __forceinline__ float exp2_fast(float x) {
    float r = rintf(x);
    float f = x - r;
    float p = 1.5403530e-4f;
    p = fmaf(p, f, 1.3333558e-3f);
    p = fmaf(p, f, 9.6181291e-3f);
    p = fmaf(p, f, 5.5504109e-2f);
    p = fmaf(p, f, 2.4022651e-1f);
    p = fmaf(p, f, 6.9314718e-1f);
    p = fmaf(p, f, 1.0f);
    return __int_as_float(__float_as_int(p) + ((int)r << 23));
}

// 1/d for positive normal d, FMA-pipe only (bit-trick seed + 3 Newton steps).
__device__ __forceinline__ float rcp_fast(float d) {
    float x = __int_as_float(0x7EF311C3 - __float_as_int(d));
    x = x * fmaf(-d, x, 2.0f);
    x = x * fmaf(-d, x, 2.0f);
    x = x * fmaf(-d, x, 2.0f);
    return x;
}

// One block per (n, action a in 0..4): 64 m's, 4 chunks of 16 m's, 2-stage
// cp.async.cg pipeline (proven Round-1/3 structure). 256 threads = 16
// half-warp groups; group g handles m-local g. Lane l16 handles tiles
// {l16, l16+16, l16+32 (l16<2)}. Epilogue reduction arrays are OVERLAID on
// ring stage 0 (last read at chunk k=2; epilogue writes only after the k=3
// barrier, whose compute reads stage 1) to fit 5 CTAs/SM.
__global__ __launch_bounds__(256, 5)
void k_main(const float* __restrict__ meta,
            const float* __restrict__ wall,
            const float* __restrict__ tp,
            const float* __restrict__ fp,
            const float* __restrict__ rp,
            const float* __restrict__ W,
            const float* __restrict__ b,
            const float* __restrict__ fanc,
            const float* __restrict__ fanm,
            const float* __restrict__ tilec,
            float* __restrict__ outm,
            float* __restrict__ outw) {
    __shared__ __align__(16) float s_buf[2][STAGE_F];   // 45,056 B
    __shared__ float s_fc[80];
    __shared__ float s_l[34];

    // epilogue overlays on stage 0
    float* s_s  = &s_buf[0][0];     // 34*17 = 578 floats
    float* s_f  = &s_buf[0][592];   // 16
    float* s_mx = &s_buf[0][608];   // 34

    const int tid  = threadIdx.x;
    const int bid  = blockIdx.x;
    const int nIdx = bid / 5;
    const int a    = bid - nIdx * 5;
    const int grp  = tid >> 4;
    const int l16  = tid & 15;

    const size_t mstart = (size_t)nIdx * 320 + a * 64;

    // prologue: issue chunk 0 first so loads fly while we compute prob_throw
    {
        const float* g0 = tp + mstart * 238;
        const float* g1 = fp + mstart * 80;
        const float* g2 = rp + mstart * 34;
        float* dst = &s_buf[0][0];
        for (int i = tid; i < 952; i += 256) cp16(dst + TP_OFF  + i * 4, g0 + i * 4);
        for (int i = tid; i < 320; i += 256) cp16(dst + FAN_OFF + i * 4, g1 + i * 4);
        for (int i = tid; i < 136; i += 256) cp16(dst + RED_OFF + i * 4, g2 + i * 4);
        asm volatile("cp.async.commit_group;\n" ::);
    }

    // fused prob_throw: per-tile Linear(11,1) then log2 (hidden under loads)
    if (tid < 34) {
        float p = b[0];
        const float* mt = meta + nIdx * 6;
        #pragma unroll
        for (int c = 0; c < 6; c++) p = fmaf(mt[c], W[c], p);
        const float* wl = wall + ((size_t)nIdx * 34 + tid) * 5;
        #pragma unroll
        for (int j = 0; j < 5; j++) p = fmaf(wl[j], W[6 + j], p);
        s_l[tid] = log2f(p);
    }
    if (tid >= 64 && tid < 144) {
        int j = tid - 64;
        s_fc[j] = fanc[j] * fanm[j];
    }
    __syncthreads();

    const float lA = s_l[l16];
    const float lB = s_l[l16 + 16];
    const float lC = (l16 < 2) ? s_l[l16 + 32] : 0.f;

    float acc0 = 0.f, acc1 = 0.f, acc2 = 0.f, facc = 0.f;

    #pragma unroll
    for (int k = 0; k < 4; k++) {
        if (k < 3) {
            const int nb = (k + 1) & 1;
            const size_t mo = mstart + (size_t)(k + 1) * 16;
            const float* g0 = tp + mo * 238;
            const float* g1 = fp + mo * 80;
            const float* g2 = rp + mo * 34;
            float* dst = &s_buf[nb][0];
            for (int i = tid; i < 952; i += 256) cp16(dst + TP_OFF  + i * 4, g0 + i * 4);
            for (int i = tid; i < 320; i += 256) cp16(dst + FAN_OFF + i * 4, g1 + i * 4);
            for (int i = tid; i < 136; i += 256) cp16(dst + RED_OFF + i * 4, g2 + i * 4);
            asm volatile("cp.async.commit_group;\n" ::);
            asm volatile("cp.async.wait_group 1;\n" ::);
        } else {
            asm volatile("cp.async.wait_group 0;\n" ::);
        }
        __syncthreads();

        const int cb = k & 1;
        const float* tpb = &s_buf[cb][TP_OFF]  + grp * 238;
        const float* fnb = &s_buf[cb][FAN_OFF] + grp * 80;
        const float* rdb = &s_buf[cb][RED_OFF] + grp * 34;

        // fan preference sum (80 = 5*16)
        float fs = 0.f;
        #pragma unroll
        for (int j = 0; j < 5; j++) {
            int jj = l16 + (j << 4);
            fs = fmaf(fnb[jj], s_fc[jj], fs);
        }

        // terms_summed = t0*p^tnc + t6 + (t3*t2/t4)*t5
        //             == ((t0*e + t6)*t4 + t3*t2*t5) / t4   (hoist the divide)
        float pn, ph;
        {
            const float* c = tpb + l16 * 7;
            float e = exp2_fast(c[1] * lA);
            pn = fmaf(fmaf(c[0], e, c[6]), c[4], c[3] * c[2] * c[5]);
            ph = c[4];
        }
        {
            const float* c = tpb + (l16 + 16) * 7;
            float e = exp2_fast(c[1] * lB);
            pn *= fmaf(fmaf(c[0], e, c[6]), c[4], c[3] * c[2] * c[5]);
            ph *= c[4];
        }
        if (l16 < 2) {
            const float* c = tpb + (l16 + 32) * 7;
            float e = exp2_fast(c[1] * lC);
            pn *= fmaf(fmaf(c[0], e, c[6]), c[4], c[3] * c[2] * c[5]);
            ph *= c[4];
        }

        // butterfly product/sum over the 16-lane group (xor masks stay in-half)
        #pragma unroll
        for (int o = 8; o >= 1; o >>= 1) {
            pn *= __shfl_xor_sync(0xffffffffu, pn, o);
            ph *= __shfl_xor_sync(0xffffffffu, ph, o);
            fs += __shfl_xor_sync(0xffffffffu, fs, o);
        }

        float fpt = pn * rcp_fast(ph) * 100.f * fs;

        acc0 = fmaf(rdb[l16],      fpt, acc0);
        acc1 = fmaf(rdb[l16 + 16], fpt, acc1);
        if (l16 < 2) acc2 = fmaf(rdb[l16 + 32], fpt, acc2);
        facc += fpt;
        __syncthreads();   // buffer cb free for reuse by the next issue
    }

    // cross-group reduction (writes overlay stage 0; k=3 compute read stage 1)
    s_s[l16 * 17 + grp]        = acc0;
    s_s[(l16 + 16) * 17 + grp] = acc1;
    if (l16 < 2) s_s[(l16 + 32) * 17 + grp] = acc2;
    if (l16 == 0) s_f[grp] = facc;
    __syncthreads();

    if (tid < 34) {
        float tb = 0.f;
        #pragma unroll
        for (int g = 0; g < 16; g++) tb += s_s[tid * 17 + g];
        if (a == 0) outw[nIdx * 34 + tid] = tb * tilec[tid];
        s_mx[tid] = tb;
    }
    __syncthreads();

    if (tid == 0) {
        float v;
        if (a == 0) {
            float fps = 0.f;
            #pragma unroll
            for (int g = 0; g < 16; g++) fps += s_f[g];
            v = fps;                       // final_prob_ops[:,0] overrides slot 0
        } else {
            float mx = s_mx[0];
            #pragma unroll
            for (int t = 1; t < 34; t++) mx = fmaxf(mx, s_mx[t]);
            v = mx;
        }
        outm[nIdx * 5 + a] = v;
    }
}

extern "C" void kernel_launch(void* const* d_in, const int* in_sizes, int n_in,
                              void* d_out, int out_size) {
    const float* meta  = (const float*)d_in[0];
    const float* wall  = (const float*)d_in[1];
    const float* tp    = (const float*)d_in[2];
    const float* fp    = (const float*)d_in[3];
    const float* rp    = (const float*)d_in[4];
    // d_in[5] (count_prep), d_in[6] (chi_peng_count_remain) unused by the reference
    const float* W     = (const float*)d_in[7];
    const float* b     = (const float*)d_in[8];
    const float* fanc  = (const float*)d_in[9];
    const float* fanm  = (const float*)d_in[10];
    const float* tilec = (const float*)d_in[11];

    int n = in_sizes[0] / 6;   // 1024

    float* outm = (float*)d_out;          // (n,5)
    float* outw = outm + (size_t)n * 5;   // (n,34)

    k_main<<<n * 5, 256>>>(meta, wall, tp, fp, rp, W, b, fanc, fanm, tilec, outm, outw);
}

// round 6
// speedup vs baseline: 1.0371x; 1.0250x over previous
#include <cuda_runtime.h>

// Per stage: 16 m * (34*7) tp | 16 m * 80 fan | 16 m * 34 red
#define TP_OFF   0
#define FAN_OFF  3808
#define RED_OFF  5088
#define STAGE_F  5632
#define GRID     608           // 152 SMs * 4 CTAs (GB300)

__device__ __forceinline__ void cp16(float* s, const float* g) {
    unsigned sa = (unsigned)__cvta_generic_to_shared(s);
    asm volatile("cp.async.cg.shared.global [%0], [%1], 16;\n" :: "r"(sa), "l"(g));
}

// 2^x for x in ~[-4, 1], FMA-pipe only. Degree-6 poly, rel err ~1e-7.
__device__ __forceinline__ float exp2_fast(float x) {
    float r = rintf(x);
    float f = x - r;
    float p = 1.5403530e-4f;
    p = fmaf(p, f, 1.3333558e-3f);
    p = fmaf(p, f, 9.6181291e-3f);
    p = fmaf(p, f, 5.5504109e-2f);
    p = fmaf(p, f, 2.4022651e-1f);
    p = fmaf(p, f, 6.9314718e-1f);
    p = fmaf(p, f, 1.0f);
    return __int_as_float(__float_as_int(p) + ((int)r << 23));
}

// 1/d for positive normal d, FMA-pipe only (bit-trick seed + 3 Newton steps).
__device__ __forceinline__ float rcp_fast(float d) {
    float x = __int_as_float(0x7EF311C3 - __float_as_int(d));
    x = x * fmaf(-d, x, 2.0f);
    x = x * fmaf(-d, x, 2.0f);
    x = x * fmaf(-d, x, 2.0f);
    return x;
}

// Persistent kernel: 608 CTAs, each loops over units u = bid + i*GRID (u < n*5).
// Unit u = (nIdx = u/5, a = u%5); its m-range start is simply 64*u.
// Per unit: 4 chunks of 16 m's through the proven 2-stage cp.async.cg pipeline,
// which runs CONTINUOUSLY across unit boundaries (next unit's chunk 0 is in
// flight while this unit's epilogue reduces). 256 threads = 16 half-warp
// groups (group = m), lane l16 handles tiles {l16, l16+16, l16+32(l16<2)}.
__global__ __launch_bounds__(256, 4)
void k_main(const float* __restrict__ meta,
            const float* __restrict__ wall,
            const float* __restrict__ tp,
            const float* __restrict__ fp,
            const float* __restrict__ rp,
            const float* __restrict__ W,
            const float* __restrict__ b,
            const float* __restrict__ fanc,
            const float* __restrict__ fanm,
            const float* __restrict__ tilec,
            float* __restrict__ outm,
            float* __restrict__ outw,
            int NU) {
    __shared__ __align__(16) float s_buf[2][STAGE_F];  // 45056 B
    __shared__ float s_fc[80];
    __shared__ float s_l[34];
    __shared__ float s_s[34 * 17];
    __shared__ float s_f[16];
    __shared__ float s_mx[34];

    const int tid = threadIdx.x;
    const int bid = blockIdx.x;
    const int grp = tid >> 4;
    const int l16 = tid & 15;

    const int cnt   = (NU - bid + GRID - 1) / GRID;   // units for this CTA
    if (cnt <= 0) return;
    const int total = cnt * 4;                        // chunks for this CTA

    // ---- issue chunk j into buffer j&1 ----
    auto issue = [&](int j) {
        const int u = bid + (j >> 2) * GRID;
        const size_t m0 = (size_t)u * 64 + (size_t)(j & 3) * 16;
        const float* g0 = tp + m0 * 238;
        const float* g1 = fp + m0 * 80;
        const float* g2 = rp + m0 * 34;
        float* dst = &s_buf[j & 1][0];
        for (int i = tid; i < 952; i += 256) cp16(dst + TP_OFF  + i * 4, g0 + i * 4);
        for (int i = tid; i < 320; i += 256) cp16(dst + FAN_OFF + i * 4, g1 + i * 4);
        for (int i = tid; i < 136; i += 256) cp16(dst + RED_OFF + i * 4, g2 + i * 4);
        asm volatile("cp.async.commit_group;\n" ::);
    };

    // ---- prologue: chunk 0 in flight, then one-time constants + unit-0 s_l ----
    issue(0);
    if (tid >= 64 && tid < 144) {
        int j = tid - 64;
        s_fc[j] = fanc[j] * fanm[j];
    }
    if (tid < 34) {
        const int nIdx0 = bid / 5;
        float p = b[0];
        const float* mt = meta + nIdx0 * 6;
        #pragma unroll
        for (int c = 0; c < 6; c++) p = fmaf(mt[c], W[c], p);
        const float* wl = wall + ((size_t)nIdx0 * 34 + tid) * 5;
        #pragma unroll
        for (int j = 0; j < 5; j++) p = fmaf(wl[j], W[6 + j], p);
        s_l[tid] = log2f(p);
    }

    float lA = 0.f, lB = 0.f, lC = 0.f;
    float acc0 = 0.f, acc1 = 0.f, acc2 = 0.f, facc = 0.f;

    for (int j = 0; j < total; j++) {
        if (j + 1 < total) {
            issue(j + 1);
            asm volatile("cp.async.wait_group 1;\n" ::);
        } else {
            asm volatile("cp.async.wait_group 0;\n" ::);
        }
        __syncthreads();

        if ((j & 3) == 0) {   // unit start: refresh prob_throw logs
            lA = s_l[l16];
            lB = s_l[l16 + 16];
            lC = (l16 < 2) ? s_l[l16 + 32] : 0.f;
        }

        const int cb = j & 1;
        const float* tpb = &s_buf[cb][TP_OFF]  + grp * 238;
        const float* fnb = &s_buf[cb][FAN_OFF] + grp * 80;
        const float* rdb = &s_buf[cb][RED_OFF] + grp * 34;

        // fan preference sum (80 = 5*16)
        float fs = 0.f;
        #pragma unroll
        for (int q = 0; q < 5; q++) {
            int jj = l16 + (q << 4);
            fs = fmaf(fnb[jj], s_fc[jj], fs);
        }

        // terms_summed = t0*p^tnc + t6 + (t3*t2/t4)*t5
        //             == ((t0*e + t6)*t4 + t3*t2*t5) / t4   (hoisted divide)
        float pn, ph;
        {
            const float* c = tpb + l16 * 7;
            float e = exp2_fast(c[1] * lA);
            pn = fmaf(fmaf(c[0], e, c[6]), c[4], c[3] * c[2] * c[5]);
            ph = c[4];
        }
        {
            const float* c = tpb + (l16 + 16) * 7;
            float e = exp2_fast(c[1] * lB);
            pn *= fmaf(fmaf(c[0], e, c[6]), c[4], c[3] * c[2] * c[5]);
            ph *= c[4];
        }
        if (l16 < 2) {
            const float* c = tpb + (l16 + 32) * 7;
            float e = exp2_fast(c[1] * lC);
            pn *= fmaf(fmaf(c[0], e, c[6]), c[4], c[3] * c[2] * c[5]);
            ph *= c[4];
        }

        // butterfly product/sum over the 16-lane group
        #pragma unroll
        for (int o = 8; o >= 1; o >>= 1) {
            pn *= __shfl_xor_sync(0xffffffffu, pn, o);
            ph *= __shfl_xor_sync(0xffffffffu, ph, o);
            fs += __shfl_xor_sync(0xffffffffu, fs, o);
        }

        float fpt = pn * rcp_fast(ph) * 100.f * fs;

        acc0 = fmaf(rdb[l16],      fpt, acc0);
        acc1 = fmaf(rdb[l16 + 16], fpt, acc1);
        if (l16 < 2) acc2 = fmaf(rdb[l16 + 32], fpt, acc2);
        facc += fpt;
        __syncthreads();   // buffer cb consumed; safe for reuse by issue(j+2)

        if ((j & 3) == 3) {
            // ---- unit epilogue (next unit's chunk 0 already streaming) ----
            const int u    = bid + (j >> 2) * GRID;
            const int nIdx = u / 5;
            const int a    = u - nIdx * 5;

            s_s[l16 * 17 + grp]        = acc0;
            s_s[(l16 + 16) * 17 + grp] = acc1;
            if (l16 < 2) s_s[(l16 + 32) * 17 + grp] = acc2;
            if (l16 == 0) s_f[grp] = facc;
            __syncthreads();

            if (tid < 34) {
                float tb = 0.f;
                #pragma unroll
                for (int g = 0; g < 16; g++) tb += s_s[tid * 17 + g];
                if (a == 0) outw[nIdx * 34 + tid] = tb * tilec[tid];
                s_mx[tid] = tb;
            }
            // threads 64..97: compute next unit's prob_throw logs in parallel
            if (tid >= 64 && tid < 98) {
                const int nu = u + GRID;
                if (nu < NU) {
                    const int t   = tid - 64;
                    const int nn  = nu / 5;
                    float p = b[0];
                    const float* mt = meta + nn * 6;
                    #pragma unroll
                    for (int c = 0; c < 6; c++) p = fmaf(mt[c], W[c], p);
                    const float* wl = wall + ((size_t)nn * 34 + t) * 5;
                    #pragma unroll
                    for (int q = 0; q < 5; q++) p = fmaf(wl[q], W[6 + q], p);
                    s_l[t] = log2f(p);
                }
            }
            __syncthreads();

            if (tid == 0) {
                float v;
                if (a == 0) {
                    float fps = 0.f;
                    #pragma unroll
                    for (int g = 0; g < 16; g++) fps += s_f[g];
                    v = fps;   // final_prob_ops[:,0] overrides slot 0
                } else {
                    float mx = s_mx[0];
                    #pragma unroll
                    for (int t = 1; t < 34; t++) mx = fmaxf(mx, s_mx[t]);
                    v = mx;
                }
                outm[nIdx * 5 + a] = v;
            }

            acc0 = acc1 = acc2 = facc = 0.f;
        }
    }
}

extern "C" void kernel_launch(void* const* d_in, const int* in_sizes, int n_in,
                              void* d_out, int out_size) {
    const float* meta  = (const float*)d_in[0];
    const float* wall  = (const float*)d_in[1];
    const float* tp    = (const float*)d_in[2];
    const float* fp    = (const float*)d_in[3];
    const float* rp    = (const float*)d_in[4];
    // d_in[5] (count_prep), d_in[6] (chi_peng_count_remain) unused by the reference
    const float* W     = (const float*)d_in[7];
    const float* b     = (const float*)d_in[8];
    const float* fanc  = (const float*)d_in[9];
    const float* fanm  = (const float*)d_in[10];
    const float* tilec = (const float*)d_in[11];

    int n  = in_sizes[0] / 6;   // 1024
    int NU = n * 5;

    float* outm = (float*)d_out;          // (n,5)
    float* outw = outm + (size_t)n * 5;   // (n,34)

    int grid = (NU < GRID) ? NU : GRID;
    k_main<<<grid, 256>>>(meta, wall, tp, fp, rp, W, b, fanc, fanm, tilec,
                          outm, outw, NU);
}